// round 15
// baseline (speedup 1.0000x reference)
#include <cuda_runtime.h>

// Problem constants
#define B_ 2
#define T_ 1024
#define C_ 768
#define H_ 12
#define D_ 64
#define L_ 6
#define V_ 32000
#define F_ 3072          // 4*C
#define M_ (B_*T_)       // 2048 rows

// ---------------------------------------------------------------------------
// Scratch: __device__ globals (no runtime allocation allowed)
// ---------------------------------------------------------------------------
static __device__ float g_h[M_*C_];          // residual stream
static __device__ float g_ln[M_*C_];         // layernorm output
static __device__ float g_qkv[M_*3*C_];      // fused q|k|v, layout (m, 3C) with n = h*64+d
static __device__ float g_att[B_*H_*T_*T_];  // attention scores / weights (100 MB)
static __device__ float g_o[M_*C_];          // attention output (B,T,H*D)
static __device__ float g_ffn[M_*F_];        // FFN hidden
static __device__ float g_wqkv[L_*C_*3*C_];  // repacked QKV weights (C x 3C per layer)

// ---------------------------------------------------------------------------
// Embedding: h[b,t,c] = tok_emb[x[b,t],c] + pos_emb[t,c]
// ---------------------------------------------------------------------------
__global__ void k_embed(const int* __restrict__ x, const float* __restrict__ tok,
                        const float* __restrict__ pos) {
    int i = blockIdx.x * blockDim.x + threadIdx.x;
    if (i >= M_*C_) return;
    int c = i % C_;
    int m = i / C_;
    int t = m % T_;
    g_h[i] = tok[(long)x[m]*C_ + c] + pos[t*C_ + c];
}

// ---------------------------------------------------------------------------
// Repack Wq/Wk/Wv (L,H,C,D) -> g_wqkv[l][k][n], n = sel*768 + h*64 + d
// ---------------------------------------------------------------------------
__global__ void k_pack(const float* __restrict__ Wq, const float* __restrict__ Wk,
                       const float* __restrict__ Wv) {
    int i = blockIdx.x * blockDim.x + threadIdx.x;
    if (i >= L_*C_*3*C_) return;
    int n = i % (3*C_);
    int r = i / (3*C_);
    int k = r % C_;
    int l = r / C_;
    int sel = n / C_;
    int hd  = n % C_;
    int h = hd / D_, d = hd % D_;
    const float* W = (sel == 0) ? Wq : (sel == 1 ? Wk : Wv);
    g_wqkv[i] = W[(((l*H_ + h)*C_) + k)*D_ + d];
}

// ---------------------------------------------------------------------------
// Block reductions
// ---------------------------------------------------------------------------
__device__ __forceinline__ float warpSum(float v) {
#pragma unroll
    for (int o = 16; o > 0; o >>= 1) v += __shfl_xor_sync(0xffffffffu, v, o);
    return v;
}
__device__ __forceinline__ float warpMax(float v) {
#pragma unroll
    for (int o = 16; o > 0; o >>= 1) v = fmaxf(v, __shfl_xor_sync(0xffffffffu, v, o));
    return v;
}
__device__ float blockSum(float v, float* sh) {
    __syncthreads();
    v = warpSum(v);
    if ((threadIdx.x & 31) == 0) sh[threadIdx.x >> 5] = v;
    __syncthreads();
    if (threadIdx.x < 32) {
        float t = (threadIdx.x < (blockDim.x >> 5)) ? sh[threadIdx.x] : 0.f;
        t = warpSum(t);
        if (threadIdx.x == 0) sh[0] = t;
    }
    __syncthreads();
    return sh[0];
}
__device__ float blockMax(float v, float* sh) {
    __syncthreads();
    v = warpMax(v);
    if ((threadIdx.x & 31) == 0) sh[threadIdx.x >> 5] = v;
    __syncthreads();
    if (threadIdx.x < 32) {
        float t = (threadIdx.x < (blockDim.x >> 5)) ? sh[threadIdx.x] : -1e30f;
        t = warpMax(t);
        if (threadIdx.x == 0) sh[0] = t;
    }
    __syncthreads();
    return sh[0];
}

// ---------------------------------------------------------------------------
// LayerNorm over C=768 (one 256-thread block per row, 3 elems/thread)
// ---------------------------------------------------------------------------
__global__ void k_ln(const float* __restrict__ in, float* __restrict__ out,
                     const float* __restrict__ g, const float* __restrict__ b) {
    __shared__ float sh[32];
    int row = blockIdx.x;
    const float* xr = in + (long)row * C_;
    float v0 = xr[threadIdx.x];
    float v1 = xr[threadIdx.x + 256];
    float v2 = xr[threadIdx.x + 512];
    float s = blockSum(v0 + v1 + v2, sh);
    float mean = s * (1.f / C_);
    float d0 = v0 - mean, d1 = v1 - mean, d2 = v2 - mean;
    float q = blockSum(d0*d0 + d1*d1 + d2*d2, sh);
    float rstd = rsqrtf(q * (1.f / C_) + 1e-5f);
    float* orow = out + (long)row * C_;
    orow[threadIdx.x]       = d0 * rstd * g[threadIdx.x]       + b[threadIdx.x];
    orow[threadIdx.x + 256] = d1 * rstd * g[threadIdx.x + 256] + b[threadIdx.x + 256];
    orow[threadIdx.x + 512] = d2 * rstd * g[threadIdx.x + 512] + b[threadIdx.x + 512];
}

// ---------------------------------------------------------------------------
// Causal softmax over scores row (applies 1/sqrt(C) scale, zeros s>t)
// grid = B*H*T rows, 256 threads
// ---------------------------------------------------------------------------
__global__ void k_softmax() {
    __shared__ float sh[32];
    int row = blockIdx.x;
    int t = row % T_;
    float* w = g_att + (long)row * T_;
    int limit = t + 1;
    const float scale = 0.03608439182435161f;  // 768^-0.5
    float mx = -1e30f;
    for (int s = threadIdx.x; s < limit; s += blockDim.x)
        mx = fmaxf(mx, w[s]);
    mx = blockMax(mx, sh) * scale;
    float sum = 0.f;
    for (int s = threadIdx.x; s < limit; s += blockDim.x) {
        float e = __expf(w[s] * scale - mx);
        w[s] = e;
        sum += e;
    }
    sum = blockSum(sum, sh);
    float inv = 1.f / sum;
    for (int s = threadIdx.x; s < T_; s += blockDim.x)
        w[s] = (s < limit) ? w[s] * inv : 0.f;
}

// ---------------------------------------------------------------------------
// Generic tiled SGEMM.
//   C[M,N] = A[M,K] @ op(B) (+bias) (+res) (relu)
//   TB=false: B is (K,N) row-major. TB=true: B is (N,K) row-major (C = A@B^T).
// Batched via blockIdx.z: z -> (zb = z/zdiv, zh = z%zdiv), per-batch offsets.
// causal==2: skip blocks entirely above the diagonal (scores).
// causal==1: truncate K at m0+BM (AV; weights above diagonal are zero).
// Requirements (all satisfied here): M%BM==0, N%BN==0, K%BK==0, ld?%4==0,
// all base offsets multiple of 4 floats.
// ---------------------------------------------------------------------------
template<int BM, int BN, int BK, int TM, int TN, bool TB>
__global__ void __launch_bounds__((BM/TM)*(BN/TN))
k_gemm(int M, int N, int K,
       const float* __restrict__ A, int lda, long sAb, long sAh,
       const float* __restrict__ B, int ldb, long sBb, long sBh,
       float* Cc, int ldc, long sCb, long sCh,
       const float* __restrict__ bias, const float* res,
       int zdiv, int relu, int causal)
{
    constexpr int TX = BN / TN, TY = BM / TM, NT = TX * TY;
    const int tid = threadIdx.x;
    const int n0 = blockIdx.x * BN;
    const int m0 = blockIdx.y * BM;
    const int z  = blockIdx.z;
    const int zb = z / zdiv, zh = z - zb * zdiv;
    A  += (long)zb * sAb + (long)zh * sAh;
    B  += (long)zb * sBb + (long)zh * sBh;
    Cc += (long)zb * sCb + (long)zh * sCh;
    if (res) res += (long)zb * sCb + (long)zh * sCh;

    if (causal == 2 && n0 >= m0 + BM) return;   // fully-masked score block
    const int Keff = (causal == 1) ? min(K, m0 + BM) : K;

    __shared__ float As[BK][BM];
    __shared__ float Bs[BK][BN];

    const int tx = tid % TX, ty = tid / TX;
    float acc[TM][TN];
#pragma unroll
    for (int i = 0; i < TM; i++)
#pragma unroll
        for (int j = 0; j < TN; j++) acc[i][j] = 0.f;

    for (int kt = 0; kt < Keff; kt += BK) {
        __syncthreads();
        // A tile: BM x BK, transposed into As[k][m]
#pragma unroll
        for (int i = tid; i < BM * BK / 4; i += NT) {
            int r = i / (BK / 4), c = i % (BK / 4);
            float4 v = *reinterpret_cast<const float4*>(A + (long)(m0 + r) * lda + kt + c * 4);
            As[c*4+0][r] = v.x; As[c*4+1][r] = v.y; As[c*4+2][r] = v.z; As[c*4+3][r] = v.w;
        }
        if (TB) {
            // B tile from (N,K) row-major, transposed into Bs[k][n]
#pragma unroll
            for (int i = tid; i < BN * BK / 4; i += NT) {
                int r = i / (BK / 4), c = i % (BK / 4);
                float4 v = *reinterpret_cast<const float4*>(B + (long)(n0 + r) * ldb + kt + c * 4);
                Bs[c*4+0][r] = v.x; Bs[c*4+1][r] = v.y; Bs[c*4+2][r] = v.z; Bs[c*4+3][r] = v.w;
            }
        } else {
            // B tile from (K,N) row-major
#pragma unroll
            for (int i = tid; i < BK * BN / 4; i += NT) {
                int r = i / (BN / 4), c = i % (BN / 4);
                float4 v = *reinterpret_cast<const float4*>(B + (long)(kt + r) * ldb + n0 + c * 4);
                *reinterpret_cast<float4*>(&Bs[r][c * 4]) = v;
            }
        }
        __syncthreads();
#pragma unroll
        for (int k = 0; k < BK; k++) {
            alignas(16) float ra[TM];
            alignas(16) float rb[TN];
#pragma unroll
            for (int i = 0; i < TM; i += 4)
                *reinterpret_cast<float4*>(&ra[i]) =
                    *reinterpret_cast<const float4*>(&As[k][ty * TM + i]);
#pragma unroll
            for (int j = 0; j < TN; j += 4)
                *reinterpret_cast<float4*>(&rb[j]) =
                    *reinterpret_cast<const float4*>(&Bs[k][tx * TN + j]);
#pragma unroll
            for (int i = 0; i < TM; i++)
#pragma unroll
                for (int j = 0; j < TN; j++)
                    acc[i][j] = fmaf(ra[i], rb[j], acc[i][j]);
        }
    }

    // Epilogue: bias + residual + relu, vectorized stores
#pragma unroll
    for (int i = 0; i < TM; i++) {
        int mm = m0 + ty * TM + i;
#pragma unroll
        for (int j = 0; j < TN; j += 4) {
            int nn = n0 + tx * TN + j;
            float4 v = make_float4(acc[i][j], acc[i][j+1], acc[i][j+2], acc[i][j+3]);
            if (bias) {
                v.x += bias[nn];   v.y += bias[nn+1];
                v.z += bias[nn+2]; v.w += bias[nn+3];
            }
            if (res) {
                float4 r4 = *reinterpret_cast<const float4*>(res + (long)mm * ldc + nn);
                v.x += r4.x; v.y += r4.y; v.z += r4.z; v.w += r4.w;
            }
            if (relu) {
                v.x = fmaxf(v.x, 0.f); v.y = fmaxf(v.y, 0.f);
                v.z = fmaxf(v.z, 0.f); v.w = fmaxf(v.w, 0.f);
            }
            *reinterpret_cast<float4*>(Cc + (long)mm * ldc + nn) = v;
        }
    }
}

// ---------------------------------------------------------------------------
// Host launcher (graph-capturable: kernel launches + symbol-address queries only)
// ---------------------------------------------------------------------------
extern "C" void kernel_launch(void* const* d_in, const int* in_sizes, int n_in,
                              void* d_out, int out_size) {
    const int*   x    = (const int*)  d_in[0];
    const float* tok  = (const float*)d_in[1];
    const float* pos  = (const float*)d_in[2];
    const float* Wq   = (const float*)d_in[3];
    const float* Wk   = (const float*)d_in[4];
    const float* Wv   = (const float*)d_in[5];
    const float* Wo   = (const float*)d_in[6];
    const float* bo   = (const float*)d_in[7];
    const float* ln1g = (const float*)d_in[8];
    const float* ln1b = (const float*)d_in[9];
    const float* ln2g = (const float*)d_in[10];
    const float* ln2b = (const float*)d_in[11];
    const float* W1   = (const float*)d_in[12];
    const float* b1   = (const float*)d_in[13];
    const float* W2   = (const float*)d_in[14];
    const float* b2   = (const float*)d_in[15];
    const float* lnfg = (const float*)d_in[16];
    const float* lnfb = (const float*)d_in[17];
    const float* Wh   = (const float*)d_in[18];
    const float* bh   = (const float*)d_in[19];
    float* out = (float*)d_out;
    (void)in_sizes; (void)n_in; (void)out_size;

    float *p_h, *p_ln, *p_qkv, *p_att, *p_o, *p_ffn, *p_w;
    cudaGetSymbolAddress((void**)&p_h,   g_h);
    cudaGetSymbolAddress((void**)&p_ln,  g_ln);
    cudaGetSymbolAddress((void**)&p_qkv, g_qkv);
    cudaGetSymbolAddress((void**)&p_att, g_att);
    cudaGetSymbolAddress((void**)&p_o,   g_o);
    cudaGetSymbolAddress((void**)&p_ffn, g_ffn);
    cudaGetSymbolAddress((void**)&p_w,   g_wqkv);

    k_embed<<<(M_*C_ + 255)/256, 256>>>(x, tok, pos);
    k_pack<<<(L_*C_*3*C_ + 255)/256, 256>>>(Wq, Wk, Wv);

    for (int l = 0; l < L_; l++) {
        // ln1
        k_ln<<<M_, 256>>>(p_h, p_ln, ln1g + l*C_, ln1b + l*C_);

        // QKV: (2048 x 2304 x 768)
        k_gemm<128,128,8,8,8,false><<<dim3(3*C_/128, M_/128, 1), 256>>>(
            M_, 3*C_, C_,
            p_ln, C_, 0, 0,
            p_w + (long)l*C_*3*C_, 3*C_, 0, 0,
            p_qkv, 3*C_, 0, 0,
            nullptr, nullptr, 1, 0, 0);

        // scores = q @ k^T per (b,h); skip fully-masked upper blocks
        k_gemm<128,128,8,8,8,true><<<dim3(T_/128, T_/128, B_*H_), 256>>>(
            T_, T_, D_,
            p_qkv,      3*C_, (long)T_*3*C_, D_,   // q
            p_qkv + C_, 3*C_, (long)T_*3*C_, D_,   // k
            p_att, T_, (long)H_*T_*T_, (long)T_*T_,
            nullptr, nullptr, H_, 0, 2);

        // causal softmax (applies scale, zeros above diagonal)
        k_softmax<<<B_*H_*T_, 256>>>();

        // o = w @ v per (b,h), K truncated at diagonal
        k_gemm<128,64,8,8,4,false><<<dim3(1, T_/128, B_*H_), 256>>>(
            T_, D_, T_,
            p_att, T_, (long)H_*T_*T_, (long)T_*T_,
            p_qkv + 2*C_, 3*C_, (long)T_*3*C_, D_,   // v
            p_o, C_, (long)T_*C_, D_,
            nullptr, nullptr, H_, 0, 1);

        // h = h + o @ Wo + bo
        k_gemm<128,128,8,8,8,false><<<dim3(C_/128, M_/128, 1), 256>>>(
            M_, C_, C_,
            p_o, C_, 0, 0,
            Wo + (long)l*C_*C_, C_, 0, 0,
            p_h, C_, 0, 0,
            bo + l*C_, p_h, 1, 0, 0);

        // ln2
        k_ln<<<M_, 256>>>(p_h, p_ln, ln2g + l*C_, ln2b + l*C_);

        // ffn hidden = relu(ln @ W1 + b1)
        k_gemm<128,128,8,8,8,false><<<dim3(F_/128, M_/128, 1), 256>>>(
            M_, F_, C_,
            p_ln, C_, 0, 0,
            W1 + (long)l*C_*F_, F_, 0, 0,
            p_ffn, F_, 0, 0,
            b1 + l*F_, nullptr, 1, 1, 0);

        // h = h + hidden @ W2 + b2
        k_gemm<128,128,8,8,8,false><<<dim3(C_/128, M_/128, 1), 256>>>(
            M_, C_, F_,
            p_ffn, F_, 0, 0,
            W2 + (long)l*F_*C_, C_, 0, 0,
            p_h, C_, 0, 0,
            b2 + l*C_, p_h, 1, 0, 0);
    }

    // final layernorm + LM head
    k_ln<<<M_, 256>>>(p_h, p_ln, lnfg, lnfb);
    k_gemm<128,128,8,8,8,false><<<dim3(V_/128, M_/128, 1), 256>>>(
        M_, V_, C_,
        p_ln, C_, 0, 0,
        Wh, V_, 0, 0,
        out, V_, 0, 0,
        bh, nullptr, 1, 0, 0);
}

// round 16
// speedup vs baseline: 1.0017x; 1.0017x over previous
#include <cuda_runtime.h>

// Problem constants
#define B_ 2
#define T_ 1024
#define C_ 768
#define H_ 12
#define D_ 64
#define L_ 6
#define V_ 32000
#define F_ 3072          // 4*C
#define M_ (B_*T_)       // 2048 rows

// ---------------------------------------------------------------------------
// Scratch: __device__ globals (no runtime allocation allowed)
// ---------------------------------------------------------------------------
static __device__ float g_h[M_*C_];          // residual stream
static __device__ float g_ln[M_*C_];         // layernorm output
static __device__ float g_qkv[M_*3*C_];      // fused q|k|v, layout (m, 3C) with n = h*64+d
static __device__ float g_att[B_*H_*T_*T_];  // attention scores / weights (100 MB)
static __device__ float g_o[M_*C_];          // attention output (B,T,H*D)
static __device__ float g_ffn[M_*F_];        // FFN hidden
static __device__ float g_wqkv[L_*C_*3*C_];  // repacked QKV weights (C x 3C per layer)

// ---------------------------------------------------------------------------
// Embedding: h[b,t,c] = tok_emb[x[b,t],c] + pos_emb[t,c]
// ---------------------------------------------------------------------------
__global__ void k_embed(const int* __restrict__ x, const float* __restrict__ tok,
                        const float* __restrict__ pos) {
    int i = blockIdx.x * blockDim.x + threadIdx.x;
    if (i >= M_*C_) return;
    int c = i % C_;
    int m = i / C_;
    int t = m % T_;
    g_h[i] = tok[(long)x[m]*C_ + c] + pos[t*C_ + c];
}

// ---------------------------------------------------------------------------
// Repack Wq/Wk/Wv (L,H,C,D) -> g_wqkv[l][k][n], n = sel*768 + h*64 + d
// ---------------------------------------------------------------------------
__global__ void k_pack(const float* __restrict__ Wq, const float* __restrict__ Wk,
                       const float* __restrict__ Wv) {
    int i = blockIdx.x * blockDim.x + threadIdx.x;
    if (i >= L_*C_*3*C_) return;
    int n = i % (3*C_);
    int r = i / (3*C_);
    int k = r % C_;
    int l = r / C_;
    int sel = n / C_;
    int hd  = n % C_;
    int h = hd / D_, d = hd % D_;
    const float* W = (sel == 0) ? Wq : (sel == 1 ? Wk : Wv);
    g_wqkv[i] = W[(((l*H_ + h)*C_) + k)*D_ + d];
}

// ---------------------------------------------------------------------------
// Block reductions
// ---------------------------------------------------------------------------
__device__ __forceinline__ float warpSum(float v) {
#pragma unroll
    for (int o = 16; o > 0; o >>= 1) v += __shfl_xor_sync(0xffffffffu, v, o);
    return v;
}
__device__ __forceinline__ float warpMax(float v) {
#pragma unroll
    for (int o = 16; o > 0; o >>= 1) v = fmaxf(v, __shfl_xor_sync(0xffffffffu, v, o));
    return v;
}
__device__ float blockSum(float v, float* sh) {
    __syncthreads();
    v = warpSum(v);
    if ((threadIdx.x & 31) == 0) sh[threadIdx.x >> 5] = v;
    __syncthreads();
    if (threadIdx.x < 32) {
        float t = (threadIdx.x < (blockDim.x >> 5)) ? sh[threadIdx.x] : 0.f;
        t = warpSum(t);
        if (threadIdx.x == 0) sh[0] = t;
    }
    __syncthreads();
    return sh[0];
}
__device__ float blockMax(float v, float* sh) {
    __syncthreads();
    v = warpMax(v);
    if ((threadIdx.x & 31) == 0) sh[threadIdx.x >> 5] = v;
    __syncthreads();
    if (threadIdx.x < 32) {
        float t = (threadIdx.x < (blockDim.x >> 5)) ? sh[threadIdx.x] : -1e30f;
        t = warpMax(t);
        if (threadIdx.x == 0) sh[0] = t;
    }
    __syncthreads();
    return sh[0];
}

// ---------------------------------------------------------------------------
// LayerNorm over C=768 (one 256-thread block per row, 3 elems/thread)
// ---------------------------------------------------------------------------
__global__ void k_ln(const float* __restrict__ in, float* __restrict__ out,
                     const float* __restrict__ g, const float* __restrict__ b) {
    __shared__ float sh[32];
    int row = blockIdx.x;
    const float* xr = in + (long)row * C_;
    float v0 = xr[threadIdx.x];
    float v1 = xr[threadIdx.x + 256];
    float v2 = xr[threadIdx.x + 512];
    float s = blockSum(v0 + v1 + v2, sh);
    float mean = s * (1.f / C_);
    float d0 = v0 - mean, d1 = v1 - mean, d2 = v2 - mean;
    float q = blockSum(d0*d0 + d1*d1 + d2*d2, sh);
    float rstd = rsqrtf(q * (1.f / C_) + 1e-5f);
    float* orow = out + (long)row * C_;
    orow[threadIdx.x]       = d0 * rstd * g[threadIdx.x]       + b[threadIdx.x];
    orow[threadIdx.x + 256] = d1 * rstd * g[threadIdx.x + 256] + b[threadIdx.x + 256];
    orow[threadIdx.x + 512] = d2 * rstd * g[threadIdx.x + 512] + b[threadIdx.x + 512];
}

// ---------------------------------------------------------------------------
// Causal softmax over scores row (applies 1/sqrt(C) scale, zeros s>t)
// grid = B*H*T rows, 256 threads
// ---------------------------------------------------------------------------
__global__ void k_softmax() {
    __shared__ float sh[32];
    int row = blockIdx.x;
    int t = row % T_;
    float* w = g_att + (long)row * T_;
    int limit = t + 1;
    const float scale = 0.03608439182435161f;  // 768^-0.5
    float mx = -1e30f;
    for (int s = threadIdx.x; s < limit; s += blockDim.x)
        mx = fmaxf(mx, w[s]);
    mx = blockMax(mx, sh) * scale;
    float sum = 0.f;
    for (int s = threadIdx.x; s < limit; s += blockDim.x) {
        float e = __expf(w[s] * scale - mx);
        w[s] = e;
        sum += e;
    }
    sum = blockSum(sum, sh);
    float inv = 1.f / sum;
    for (int s = threadIdx.x; s < T_; s += blockDim.x)
        w[s] = (s < limit) ? w[s] * inv : 0.f;
}

// ---------------------------------------------------------------------------
// Generic tiled SGEMM.
//   C[M,N] = A[M,K] @ op(B) (+bias) (+res) (relu)
//   TB=false: B is (K,N) row-major. TB=true: B is (N,K) row-major (C = A@B^T).
// Batched via blockIdx.z: z -> (zb = z/zdiv, zh = z%zdiv), per-batch offsets.
// causal==2: skip blocks entirely above the diagonal (scores).
// causal==1: truncate K at m0+BM (AV; weights above diagonal are zero).
// Requirements (all satisfied here): M%BM==0, N%BN==0, K%BK==0, ld?%4==0,
// all base offsets multiple of 4 floats.
// ---------------------------------------------------------------------------
template<int BM, int BN, int BK, int TM, int TN, bool TB>
__global__ void __launch_bounds__((BM/TM)*(BN/TN))
k_gemm(int M, int N, int K,
       const float* __restrict__ A, int lda, long sAb, long sAh,
       const float* __restrict__ B, int ldb, long sBb, long sBh,
       float* Cc, int ldc, long sCb, long sCh,
       const float* __restrict__ bias, const float* res,
       int zdiv, int relu, int causal)
{
    constexpr int TX = BN / TN, TY = BM / TM, NT = TX * TY;
    const int tid = threadIdx.x;
    const int n0 = blockIdx.x * BN;
    const int m0 = blockIdx.y * BM;
    const int z  = blockIdx.z;
    const int zb = z / zdiv, zh = z - zb * zdiv;
    A  += (long)zb * sAb + (long)zh * sAh;
    B  += (long)zb * sBb + (long)zh * sBh;
    Cc += (long)zb * sCb + (long)zh * sCh;
    if (res) res += (long)zb * sCb + (long)zh * sCh;

    if (causal == 2 && n0 >= m0 + BM) return;   // fully-masked score block
    const int Keff = (causal == 1) ? min(K, m0 + BM) : K;

    __shared__ float As[BK][BM];
    __shared__ float Bs[BK][BN];

    const int tx = tid % TX, ty = tid / TX;
    float acc[TM][TN];
#pragma unroll
    for (int i = 0; i < TM; i++)
#pragma unroll
        for (int j = 0; j < TN; j++) acc[i][j] = 0.f;

    for (int kt = 0; kt < Keff; kt += BK) {
        __syncthreads();
        // A tile: BM x BK, transposed into As[k][m]
#pragma unroll
        for (int i = tid; i < BM * BK / 4; i += NT) {
            int r = i / (BK / 4), c = i % (BK / 4);
            float4 v = *reinterpret_cast<const float4*>(A + (long)(m0 + r) * lda + kt + c * 4);
            As[c*4+0][r] = v.x; As[c*4+1][r] = v.y; As[c*4+2][r] = v.z; As[c*4+3][r] = v.w;
        }
        if (TB) {
            // B tile from (N,K) row-major, transposed into Bs[k][n]
#pragma unroll
            for (int i = tid; i < BN * BK / 4; i += NT) {
                int r = i / (BK / 4), c = i % (BK / 4);
                float4 v = *reinterpret_cast<const float4*>(B + (long)(n0 + r) * ldb + kt + c * 4);
                Bs[c*4+0][r] = v.x; Bs[c*4+1][r] = v.y; Bs[c*4+2][r] = v.z; Bs[c*4+3][r] = v.w;
            }
        } else {
            // B tile from (K,N) row-major
#pragma unroll
            for (int i = tid; i < BK * BN / 4; i += NT) {
                int r = i / (BN / 4), c = i % (BN / 4);
                float4 v = *reinterpret_cast<const float4*>(B + (long)(kt + r) * ldb + n0 + c * 4);
                *reinterpret_cast<float4*>(&Bs[r][c * 4]) = v;
            }
        }
        __syncthreads();
#pragma unroll
        for (int k = 0; k < BK; k++) {
            alignas(16) float ra[TM];
            alignas(16) float rb[TN];
#pragma unroll
            for (int i = 0; i < TM; i += 4)
                *reinterpret_cast<float4*>(&ra[i]) =
                    *reinterpret_cast<const float4*>(&As[k][ty * TM + i]);
#pragma unroll
            for (int j = 0; j < TN; j += 4)
                *reinterpret_cast<float4*>(&rb[j]) =
                    *reinterpret_cast<const float4*>(&Bs[k][tx * TN + j]);
#pragma unroll
            for (int i = 0; i < TM; i++)
#pragma unroll
                for (int j = 0; j < TN; j++)
                    acc[i][j] = fmaf(ra[i], rb[j], acc[i][j]);
        }
    }

    // Epilogue: bias + residual + relu, vectorized stores
#pragma unroll
    for (int i = 0; i < TM; i++) {
        int mm = m0 + ty * TM + i;
#pragma unroll
        for (int j = 0; j < TN; j += 4) {
            int nn = n0 + tx * TN + j;
            float4 v = make_float4(acc[i][j], acc[i][j+1], acc[i][j+2], acc[i][j+3]);
            if (bias) {
                v.x += bias[nn];   v.y += bias[nn+1];
                v.z += bias[nn+2]; v.w += bias[nn+3];
            }
            if (res) {
                float4 r4 = *reinterpret_cast<const float4*>(res + (long)mm * ldc + nn);
                v.x += r4.x; v.y += r4.y; v.z += r4.z; v.w += r4.w;
            }
            if (relu) {
                v.x = fmaxf(v.x, 0.f); v.y = fmaxf(v.y, 0.f);
                v.z = fmaxf(v.z, 0.f); v.w = fmaxf(v.w, 0.f);
            }
            *reinterpret_cast<float4*>(Cc + (long)mm * ldc + nn) = v;
        }
    }
}

// ---------------------------------------------------------------------------
// Host launcher (graph-capturable: kernel launches + symbol-address queries only)
// ---------------------------------------------------------------------------
extern "C" void kernel_launch(void* const* d_in, const int* in_sizes, int n_in,
                              void* d_out, int out_size) {
    const int*   x    = (const int*)  d_in[0];
    const float* tok  = (const float*)d_in[1];
    const float* pos  = (const float*)d_in[2];
    const float* Wq   = (const float*)d_in[3];
    const float* Wk   = (const float*)d_in[4];
    const float* Wv   = (const float*)d_in[5];
    const float* Wo   = (const float*)d_in[6];
    const float* bo   = (const float*)d_in[7];
    const float* ln1g = (const float*)d_in[8];
    const float* ln1b = (const float*)d_in[9];
    const float* ln2g = (const float*)d_in[10];
    const float* ln2b = (const float*)d_in[11];
    const float* W1   = (const float*)d_in[12];
    const float* b1   = (const float*)d_in[13];
    const float* W2   = (const float*)d_in[14];
    const float* b2   = (const float*)d_in[15];
    const float* lnfg = (const float*)d_in[16];
    const float* lnfb = (const float*)d_in[17];
    const float* Wh   = (const float*)d_in[18];
    const float* bh   = (const float*)d_in[19];
    float* out = (float*)d_out;
    (void)in_sizes; (void)n_in; (void)out_size;

    float *p_h, *p_ln, *p_qkv, *p_att, *p_o, *p_ffn, *p_w;
    cudaGetSymbolAddress((void**)&p_h,   g_h);
    cudaGetSymbolAddress((void**)&p_ln,  g_ln);
    cudaGetSymbolAddress((void**)&p_qkv, g_qkv);
    cudaGetSymbolAddress((void**)&p_att, g_att);
    cudaGetSymbolAddress((void**)&p_o,   g_o);
    cudaGetSymbolAddress((void**)&p_ffn, g_ffn);
    cudaGetSymbolAddress((void**)&p_w,   g_wqkv);

    k_embed<<<(M_*C_ + 255)/256, 256>>>(x, tok, pos);
    k_pack<<<(L_*C_*3*C_ + 255)/256, 256>>>(Wq, Wk, Wv);

    for (int l = 0; l < L_; l++) {
        // ln1
        k_ln<<<M_, 256>>>(p_h, p_ln, ln1g + l*C_, ln1b + l*C_);

        // QKV: (2048 x 2304 x 768)
        k_gemm<128,128,8,8,8,false><<<dim3(3*C_/128, M_/128, 1), 256>>>(
            M_, 3*C_, C_,
            p_ln, C_, 0, 0,
            p_w + (long)l*C_*3*C_, 3*C_, 0, 0,
            p_qkv, 3*C_, 0, 0,
            nullptr, nullptr, 1, 0, 0);

        // scores = q @ k^T per (b,h); skip fully-masked upper blocks
        k_gemm<128,128,8,8,8,true><<<dim3(T_/128, T_/128, B_*H_), 256>>>(
            T_, T_, D_,
            p_qkv,      3*C_, (long)T_*3*C_, D_,   // q
            p_qkv + C_, 3*C_, (long)T_*3*C_, D_,   // k
            p_att, T_, (long)H_*T_*T_, (long)T_*T_,
            nullptr, nullptr, H_, 0, 2);

        // causal softmax (applies scale, zeros above diagonal)
        k_softmax<<<B_*H_*T_, 256>>>();

        // o = w @ v per (b,h), K truncated at diagonal
        k_gemm<128,64,8,8,4,false><<<dim3(1, T_/128, B_*H_), 256>>>(
            T_, D_, T_,
            p_att, T_, (long)H_*T_*T_, (long)T_*T_,
            p_qkv + 2*C_, 3*C_, (long)T_*3*C_, D_,   // v
            p_o, C_, (long)T_*C_, D_,
            nullptr, nullptr, H_, 0, 1);

        // h = h + o @ Wo + bo
        k_gemm<128,128,8,8,8,false><<<dim3(C_/128, M_/128, 1), 256>>>(
            M_, C_, C_,
            p_o, C_, 0, 0,
            Wo + (long)l*C_*C_, C_, 0, 0,
            p_h, C_, 0, 0,
            bo + l*C_, p_h, 1, 0, 0);

        // ln2
        k_ln<<<M_, 256>>>(p_h, p_ln, ln2g + l*C_, ln2b + l*C_);

        // ffn hidden = relu(ln @ W1 + b1)
        k_gemm<128,128,8,8,8,false><<<dim3(F_/128, M_/128, 1), 256>>>(
            M_, F_, C_,
            p_ln, C_, 0, 0,
            W1 + (long)l*C_*F_, F_, 0, 0,
            p_ffn, F_, 0, 0,
            b1 + l*F_, nullptr, 1, 1, 0);

        // h = h + hidden @ W2 + b2
        k_gemm<128,128,8,8,8,false><<<dim3(C_/128, M_/128, 1), 256>>>(
            M_, C_, F_,
            p_ffn, F_, 0, 0,
            W2 + (long)l*F_*C_, C_, 0, 0,
            p_h, C_, 0, 0,
            b2 + l*C_, p_h, 1, 0, 0);
    }

    // final layernorm + LM head
    k_ln<<<M_, 256>>>(p_h, p_ln, lnfg, lnfb);
    k_gemm<128,128,8,8,8,false><<<dim3(V_/128, M_/128, 1), 256>>>(
        M_, V_, C_,
        p_ln, C_, 0, 0,
        Wh, V_, 0, 0,
        out, V_, 0, 0,
        bh, nullptr, 1, 0, 0);
}